// round 7
// baseline (speedup 1.0000x reference)
#include <cuda_runtime.h>
#include <cstdint>

// ---------------------------------------------------------------------------
// StableSpikingCoreFlow: T=64, B=128, D=N=2048, L=4, OUT=1024
//
// Identity: mean_t(gathered_t @ W^T) = (mean_t gathered_t) @ W^T; next layer
// consumes mean_t(spikes) = count/64 (dyadic -> exact). Output = total spike
// counts at out_idx.
//
// Round 6: 1024 threads (32 warps/SM, 8/SMSP), 8 split-K groups of 128
// threads, per-thread 2m x 8n fma.rn.f32x2 tile (32 acc regs -> fits the
// 64-reg cap), cp.async double-buffered BK=8 tiles. Summation structure is
// bit-identical to round 5 (KSLICE=256, flush at 128 k, 64-term even/odd
// chains, tree-16 merge) -> rel_err 0.0 preserved.
// ---------------------------------------------------------------------------

#define Bc   128
#define Dc   2048
#define Nc   2048
#define Tc   64
#define Lc   4
#define OUTc 1024

#define BM 32
#define BN 64
#define BK 8
#define NTHREADS 1024
#define NGROUPS 8               // 128 threads (4 warps) per group
#define KSLICE (Dc / NGROUPS)   // 256
#define NKB (KSLICE / BK)       // 32 tiles per group

// smem tiles: rows hold BK=8 k-floats (32B), padded to 48B (12 floats);
// 16B-granule offsets 48*r mod 128 are all distinct -> conflict-free LDS.128.
#define ROWF 12
#define AS_SZ (BM * ROWF)        // 384 floats
#define BS_SZ (BN * ROWF)        // 768 floats
#define TILE_SZ (AS_SZ + BS_SZ)  // 1152 floats per group per buffer
#define PS_OFF (2 * NGROUPS * TILE_SZ)             // 18432 floats
#define NPLANES 16                                  // 8 groups x 2 k-halves
#define SMEM_FLOATS (PS_OFF + NPLANES * BM * BN)    // 51200
#define SMEM_BYTES (SMEM_FLOATS * 4)                // 204800

// scratch (no cudaMalloc allowed)
__device__ float g_G [Bc * Dc];
__device__ float g_R0[Bc * Nc];
__device__ float g_R1[Bc * Nc];

// ---------------------------------------------------------------------------
__device__ __forceinline__ void cp16(uint32_t dst, const float* src) {
    asm volatile("cp.async.cg.shared.global [%0], [%1], 16;\n"
                 :: "r"(dst), "l"(src));
}
#define CP_COMMIT() asm volatile("cp.async.commit_group;\n" ::: "memory")
#define CP_WAIT(n)  asm volatile("cp.async.wait_group %0;\n" :: "n"(n) : "memory")

__device__ __forceinline__ void ffma2(unsigned long long& c,
                                      unsigned long long a,
                                      unsigned long long b) {
    asm volatile("fma.rn.f32x2 %0, %1, %2, %0;\n" : "+l"(c) : "l"(a), "l"(b));
}

__device__ __forceinline__ float pair_sum(unsigned long long v) {
    float lo = __uint_as_float((unsigned)v);
    float hi = __uint_as_float((unsigned)(v >> 32));
    return __fadd_rn(lo, hi);
}

// exact fp32 semantics of the reference spike scan
__device__ __forceinline__ float spike_rate(float a, float thr) {
    int c;
    if (a <= 0.f) {
        c = 0;                       // thr > 0: m never exceeds thr
    } else if (a > thr) {
        c = Tc;                      // spikes every step, exactly
    } else {
        float m = 0.f; c = 0;
        for (int t = 0; t < Tc; t++) {
            m += a;
            if (m > thr) { m -= thr; c++; }
        }
    }
    return (float)c * (1.0f / Tc);
}

// ---------------------------------------------------------------------------
__global__ void gather_kernel(const float* __restrict__ Rin,
                              const int*   __restrict__ axon,
                              float*       __restrict__ G)
{
    int idx = blockIdx.x * blockDim.x + threadIdx.x;
    if (idx >= Bc * Dc) return;
    int b = idx >> 11;
    int a = idx & 2047;
    G[idx] = Rin[(b << 11) + axon[a]];
}

// ---------------------------------------------------------------------------
__global__ __launch_bounds__(NTHREADS, 1)
void layer_kernel(const float* __restrict__ G,     // [B, D]
                  const float* __restrict__ W,     // [N, D] row-major
                  const float* __restrict__ thresholds,
                  int l,
                  float* __restrict__ Rout)        // [B, N] rates = c/64
{
    extern __shared__ float sm[];

    const int tid  = threadIdx.x;
    const int g    = tid >> 7;           // split-K group 0..7 (4 warps)
    const int gt   = tid & 127;
    const int w    = gt >> 5;            // warp within group 0..3
    const int lane = gt & 31;
    const int ncol = lane & 7;           // n base 0..7
    const int mrow = lane >> 3;          // 0..3
    const int m0   = (w * 4 + mrow) * 2; // 0,2,...,30

    const int bm = blockIdx.y * BM;
    const int bn = blockIdx.x * BN;
    const int kbase = g * KSLICE;

    float* As0 = sm + (0 * NGROUPS + g) * TILE_SZ;
    float* As1 = sm + (1 * NGROUPS + g) * TILE_SZ;
    float* Bs0 = As0 + AS_SZ;
    float* Bs1 = As1 + AS_SZ;
    float* Ps  = sm + PS_OFF;

    // cp.async mapping: every thread 1 B chunk; first 64 threads also 1 A chunk
    const int brow = gt >> 1;            // 0..63
    const int bch  = gt & 1;             // 16B chunk
    const int arow = (gt & 63) >> 1;     // 0..31
    const int ach  = gt & 1;
    const bool doA = (gt < 64);

    const float* gB = W + (size_t)(bn + brow) * Dc + kbase + bch * 4;
    const float* gA = G + (size_t)(bm + arow) * Dc + kbase + ach * 4;

    const uint32_t sB0 = (uint32_t)__cvta_generic_to_shared(Bs0 + brow * ROWF + bch * 4);
    const uint32_t sB1 = (uint32_t)__cvta_generic_to_shared(Bs1 + brow * ROWF + bch * 4);
    const uint32_t sA0 = (uint32_t)__cvta_generic_to_shared(As0 + arow * ROWF + ach * 4);
    const uint32_t sA1 = (uint32_t)__cvta_generic_to_shared(As1 + arow * ROWF + ach * 4);

#define ISSUE(t, buf) do { \
        cp16((buf) ? sB1 : sB0, gB + (t) * BK); \
        if (doA) cp16((buf) ? sA1 : sA0, gA + (t) * BK); \
        CP_COMMIT(); \
    } while (0)

    // 16 packed accumulators: acc[i][j] = f32x2 (even-k, odd-k chains)
    // for output (m = m0 + i, n = ncol + 8j)
    unsigned long long acc[2][8];
#pragma unroll
    for (int i = 0; i < 2; i++)
#pragma unroll
        for (int j = 0; j < 8; j++) acc[i][j] = 0ull;

    ISSUE(0, 0);
    ISSUE(1, 1);

    for (int t = 0; t < NKB; t++) {
        if (t == NKB - 1) { CP_WAIT(0); } else { CP_WAIT(1); }
        __syncthreads();

        const float* As = (t & 1) ? As1 : As0;
        const float* Bs = (t & 1) ? Bs1 : Bs0;

#pragma unroll
        for (int h = 0; h < 2; h++) {
            ulonglong2 a0 = *reinterpret_cast<const ulonglong2*>(
                                As + (m0 + 0) * ROWF + h * 4);
            ulonglong2 a1 = *reinterpret_cast<const ulonglong2*>(
                                As + (m0 + 1) * ROWF + h * 4);
#pragma unroll
            for (int j = 0; j < 8; j++) {
                ulonglong2 b = *reinterpret_cast<const ulonglong2*>(
                                   Bs + (ncol + 8 * j) * ROWF + h * 4);
                ffma2(acc[0][j], a0.x, b.x);
                ffma2(acc[0][j], a0.y, b.y);
                ffma2(acc[1][j], a1.x, b.x);
                ffma2(acc[1][j], a1.y, b.y);
            }
        }
        __syncthreads();
        if (t + 2 < NKB) ISSUE(t + 2, t & 1);

        // flush first k-half (128 k -> 64-term chains) to partial plane g
        if (t == NKB / 2 - 1) {
#pragma unroll
            for (int i = 0; i < 2; i++)
#pragma unroll
                for (int j = 0; j < 8; j++) {
                    Ps[g * (BM * BN) + (m0 + i) * BN + (ncol + 8 * j)] =
                        pair_sum(acc[i][j]);
                    acc[i][j] = 0ull;
                }
        }
    }
#undef ISSUE

    // flush second k-half to plane 8+g
#pragma unroll
    for (int i = 0; i < 2; i++)
#pragma unroll
        for (int j = 0; j < 8; j++)
            Ps[(NGROUPS + g) * (BM * BN) + (m0 + i) * BN + (ncol + 8 * j)] =
                pair_sum(acc[i][j]);
    __syncthreads();

    // tree-16 merge + fused spike scan, 2 outputs per thread
    {
        const int idx = tid * 2;
        const int m = idx >> 6;
        const int n = idx & 63;

        float2 v[NPLANES];
#pragma unroll
        for (int p = 0; p < NPLANES; p++)
            v[p] = *(const float2*)&Ps[p * (BM * BN) + idx];

        float ex[NPLANES], ey[NPLANES];
#pragma unroll
        for (int p = 0; p < NPLANES; p++) { ex[p] = v[p].x; ey[p] = v[p].y; }
        // fixed-order pairwise tree
#pragma unroll
        for (int s = 1; s < NPLANES; s <<= 1)
#pragma unroll
            for (int p = 0; p < NPLANES; p += 2 * s) {
                ex[p] = __fadd_rn(ex[p], ex[p + s]);
                ey[p] = __fadd_rn(ey[p], ey[p + s]);
            }

        const float thr = thresholds[l];
        float2 outv;
        outv.x = spike_rate(ex[0], thr);
        outv.y = spike_rate(ey[0], thr);
        *(float2*)&Rout[(bm + m) * Nc + bn + n] = outv;
    }
}

// ---------------------------------------------------------------------------
__global__ void out_kernel(const float* __restrict__ R,
                           const int*   __restrict__ out_idx,
                           float*       __restrict__ out)
{
    int idx = blockIdx.x * blockDim.x + threadIdx.x;
    if (idx >= Bc * OUTc) return;
    int b = idx >> 10;
    int o = idx & 1023;
    out[idx] = R[(b << 11) + out_idx[o]] * (float)Tc;  // rate*64 = count, exact
}

// ---------------------------------------------------------------------------
extern "C" void kernel_launch(void* const* d_in, const int* in_sizes, int n_in,
                              void* d_out, int out_size)
{
    const float* x       = (const float*)d_in[0];   // [B, D]
    const float* W       = (const float*)d_in[1];   // [L, N, D]
    const float* thr     = (const float*)d_in[2];   // [L]
    const int*   axon    = (const int*)  d_in[3];   // [L, D]
    const int*   out_idx = (const int*)  d_in[4];   // [OUT]
    (void)in_sizes; (void)n_in; (void)out_size;

    cudaFuncSetAttribute(layer_kernel,
                         cudaFuncAttributeMaxDynamicSharedMemorySize,
                         SMEM_BYTES);

    float *G, *R0, *R1;
    cudaGetSymbolAddress((void**)&G,  g_G);
    cudaGetSymbolAddress((void**)&R0, g_R0);
    cudaGetSymbolAddress((void**)&R1, g_R1);
    float* bufs[2] = { R0, R1 };

    dim3 ggrid((Bc * Dc + 255) / 256);
    dim3 lgrid(Nc / BN, Bc / BM);   // (32, 4) = 128 blocks

    const float* rin = x;
    for (int l = 0; l < Lc; l++) {
        gather_kernel<<<ggrid, 256>>>(rin, axon + l * Dc, G);
        layer_kernel <<<lgrid, NTHREADS, SMEM_BYTES>>>(
            G, W + (size_t)l * Nc * Dc, thr, l, bufs[l & 1]);
        rin = bufs[l & 1];
    }
    out_kernel<<<(Bc * OUTc + 255) / 256, 256>>>(rin, out_idx, (float*)d_out);
}

// round 9
// speedup vs baseline: 1.5667x; 1.5667x over previous
#include <cuda_runtime.h>
#include <cuda_bf16.h>
#include <cstdint>

// ---------------------------------------------------------------------------
// StableSpikingCoreFlow, round 9: tensor-core bf16 GEMM, exact products,
// CHUNKED accumulation: mma accumulator flushed into Kahan register sums
// every 128 k-slots (the summation structure that measured rel_err 0.0 in
// rounds 2/3/5/6), splitK=8 planes + tree-8 merge, /64 exact, exact scan.
// ---------------------------------------------------------------------------

#define Bc 128
#define Dc 2048
#define Nc 2048
#define Tc 64
#define OUTc 1024

#define KT0 12288
#define KT1 6144
#define GT  256

#define ROWB 144             // 64 bf16 (128B) + 16B pad
#define ATILE (128 * ROWB)   // 18432 B
#define BTILE (64 * ROWB)    //  9216 B
#define BUFB  (ATILE + BTILE)
#define SMEMB (2 * BUFB)     // 55296 B

__device__ __nv_bfloat16 g_A[(size_t)Bc * KT0];
__device__ __nv_bfloat16 g_B[(size_t)Nc * KT0];
__device__ float g_P[8 * Bc * Nc];
__device__ float g_R0[Bc * Nc];
__device__ float g_R1[Bc * Nc];

// ---------------------------------------------------------------------------
__device__ __forceinline__ void cp16(uint32_t dst, const void* src) {
    asm volatile("cp.async.cg.shared.global [%0], [%1], 16;\n" :: "r"(dst), "l"(src));
}
#define CP_COMMIT() asm volatile("cp.async.commit_group;\n" ::: "memory")
#define CP_WAIT(n)  asm volatile("cp.async.wait_group %0;\n" :: "n"(n) : "memory")

__device__ __forceinline__ void mma16816(float* c, const uint32_t* a,
                                         uint32_t b0, uint32_t b1) {
    asm volatile(
        "mma.sync.aligned.m16n8k16.row.col.f32.bf16.bf16.f32 "
        "{%0,%1,%2,%3},{%4,%5,%6,%7},{%8,%9},{%0,%1,%2,%3};\n"
        : "+f"(c[0]), "+f"(c[1]), "+f"(c[2]), "+f"(c[3])
        : "r"(a[0]), "r"(a[1]), "r"(a[2]), "r"(a[3]), "r"(b0), "r"(b1));
}

__device__ __forceinline__ float bfround(float v) {
    return __bfloat162float(__float2bfloat16_rn(v));
}
__device__ __forceinline__ unsigned bfu(float v) {
    return (unsigned)__bfloat16_as_ushort(__float2bfloat16_rn(v));
}
__device__ __forceinline__ uint32_t pk(unsigned lo, unsigned hi) {
    return lo | (hi << 16);
}
// v = p0+p1+p2 + O(2^-25 v); residual subtractions exact
__device__ __forceinline__ void split3(float v, unsigned& u0, unsigned& u1,
                                       unsigned& u2) {
    float r1 = v - bfround(v);
    float r2 = r1 - bfround(r1);
    u0 = bfu(v); u1 = bfu(r1); u2 = bfu(r2);
}

// exact fp32 semantics of the reference spike scan; returns COUNT (0..64)
__device__ __forceinline__ float spike_count(float a, float thr) {
    int c;
    if (a <= 0.f) c = 0;
    else if (a > thr) c = Tc;
    else {
        float m = 0.f; c = 0;
        for (int t = 0; t < Tc; t++) { m += a; if (m > thr) { m -= thr; c++; } }
    }
    return (float)c;
}

// ---------------------------------------------------------------------------
// layer 0: A' pieces of v = 64*x gathered; slots [v0,v0,v0,v1,v1,v2]
__global__ void asplit0_kernel(const float* __restrict__ x,
                               const int* __restrict__ axon) {
    int idx = blockIdx.x * blockDim.x + threadIdx.x;
    if (idx >= Bc * Dc) return;
    int b = idx >> 11, a = idx & 2047;
    unsigned u0, u1, u2;
    split3(64.0f * x[(b << 11) + axon[a]], u0, u1, u2);
    uint32_t* dst = (uint32_t*)(g_A + (size_t)b * KT0 + 6 * a);
    dst[0] = pk(u0, u0); dst[1] = pk(u0, u1); dst[2] = pk(u1, u2);
}

// layer 0: B' slots [w0,w1,w2,w0,w1,w0]  (pairs (0,0)(0,1)(0,2)(1,0)(1,1)(2,0))
__global__ void wsplit0_kernel(const float* __restrict__ W) {
    int idx = blockIdx.x * blockDim.x + threadIdx.x;
    if (idx >= Nc * Dc) return;
    int n = idx >> 11, k = idx & 2047;
    unsigned u0, u1, u2;
    split3(W[idx], u0, u1, u2);
    uint32_t* dst = (uint32_t*)(g_B + (size_t)n * KT0 + 6 * k);
    dst[0] = pk(u0, u1); dst[1] = pk(u2, u0); dst[2] = pk(u1, u0);
}

// layers >=1: A' = counts (exact bf16), slots [c,c,c]; 2 k per thread
__global__ void agather1_kernel(const float* __restrict__ R,
                                const int* __restrict__ axon) {
    int idx = blockIdx.x * blockDim.x + threadIdx.x;
    if (idx >= Bc * Dc / 2) return;
    int b = idx >> 10, a = (idx & 1023) * 2;
    unsigned h0 = bfu(R[(b << 11) + axon[a]]);
    unsigned h1 = bfu(R[(b << 11) + axon[a + 1]]);
    uint32_t* dst = (uint32_t*)(g_A + (size_t)b * KT1 + 3 * a);
    dst[0] = pk(h0, h0); dst[1] = pk(h0, h1); dst[2] = pk(h1, h1);
}

// layers >=1: B' slots [w0,w1,w2]; 2 k per thread
__global__ void wsplit1_kernel(const float* __restrict__ W) {
    int idx = blockIdx.x * blockDim.x + threadIdx.x;
    if (idx >= Nc * Dc / 2) return;
    int n = idx >> 10, k = (idx & 1023) * 2;
    unsigned a0, a1, a2, b0, b1, b2;
    split3(W[(size_t)n * Dc + k], a0, a1, a2);
    split3(W[(size_t)n * Dc + k + 1], b0, b1, b2);
    uint32_t* dst = (uint32_t*)(g_B + (size_t)n * KT1 + 3 * k);
    dst[0] = pk(a0, a1); dst[1] = pk(a2, b0); dst[2] = pk(b1, b2);
}

// ---------------------------------------------------------------------------
// Block 128m x 64n, 8 warps (4m x 2n), warp tile 32m x 32n. k-phase = 64
// slots, double-buffered cp.async. Kahan fold of the mma accumulator every
// 2 phases (128 slots); final value = ks - kc (round-2 formula).
__global__ __launch_bounds__(GT, 1)
void gemm_kernel(int Ktot, int nPh) {
    extern __shared__ char smch[];
    const int tid = threadIdx.x;
    const int w = tid >> 5, lane = tid & 31;
    const int wm = w & 3, wn = w >> 2;
    const int g = lane >> 2, tig = lane & 3;
    const int bn = blockIdx.x * 64;
    const size_t k0 = (size_t)blockIdx.y * (Ktot >> 3);
    const uint32_t smb = (uint32_t)__cvta_generic_to_shared(smch);

    const __nv_bfloat16* srcs[6];
    uint32_t dsts[6];
    const int ch = tid & 7;
#pragma unroll
    for (int r = 0; r < 4; r++) {             // A: 1024 16B chunks
        int row = (tid + r * GT) >> 3;
        srcs[r] = g_A + (size_t)row * Ktot + k0 + ch * 8;
        dsts[r] = smb + row * ROWB + ch * 16;
    }
#pragma unroll
    for (int r = 4; r < 6; r++) {             // B: 512 16B chunks
        int brow = (tid + (r - 4) * GT) >> 3;
        srcs[r] = g_B + (size_t)(bn + brow) * Ktot + k0 + ch * 8;
        dsts[r] = smb + ATILE + brow * ROWB + ch * 16;
    }
#define GISSUE(p, buf) do {                                         \
        uint32_t bo = (uint32_t)(buf) * BUFB;                       \
        _Pragma("unroll")                                           \
        for (int r = 0; r < 6; r++)                                 \
            cp16(dsts[r] + bo, srcs[r] + (size_t)(p) * 64);         \
        CP_COMMIT();                                                \
    } while (0)

    float acc[2][4][4], ks[2][4][4], kc[2][4][4];
#pragma unroll
    for (int mt = 0; mt < 2; mt++)
#pragma unroll
        for (int j = 0; j < 4; j++)
#pragma unroll
            for (int q = 0; q < 4; q++) {
                acc[mt][j][q] = 0.f; ks[mt][j][q] = 0.f; kc[mt][j][q] = 0.f;
            }

    GISSUE(0, 0);
    GISSUE(1, 1);

    for (int p = 0; p < nPh; p++) {
        if (p + 1 < nPh) { CP_WAIT(1); } else { CP_WAIT(0); }
        __syncthreads();
        const char* Ab = smch + (p & 1) * BUFB;
        const char* Bb = Ab + ATILE;
#pragma unroll
        for (int kk = 0; kk < 4; kk++) {
            uint32_t a[2][4];
#pragma unroll
            for (int mt = 0; mt < 2; mt++) {
                const char* ap = Ab + (wm * 32 + mt * 16 + g) * ROWB
                               + kk * 32 + tig * 4;
                a[mt][0] = *(const uint32_t*)ap;
                a[mt][1] = *(const uint32_t*)(ap + 8 * ROWB);
                a[mt][2] = *(const uint32_t*)(ap + 16);
                a[mt][3] = *(const uint32_t*)(ap + 8 * ROWB + 16);
            }
#pragma unroll
            for (int j = 0; j < 4; j++) {
                const char* bp = Bb + (wn * 32 + j * 8 + g) * ROWB
                               + kk * 32 + tig * 4;
                uint32_t b0 = *(const uint32_t*)bp;
                uint32_t b1 = *(const uint32_t*)(bp + 16);
                mma16816(acc[0][j], a[0], b0, b1);
                mma16816(acc[1][j], a[1], b0, b1);
            }
        }
        __syncthreads();
        if (p + 2 < nPh) GISSUE(p + 2, p & 1);

        if (p & 1) {   // Kahan fold every 2 phases = 128 k-slots
#pragma unroll
            for (int mt = 0; mt < 2; mt++)
#pragma unroll
                for (int j = 0; j < 4; j++)
#pragma unroll
                    for (int q = 0; q < 4; q++) {
                        float y = __fsub_rn(acc[mt][j][q], kc[mt][j][q]);
                        float t = __fadd_rn(ks[mt][j][q], y);
                        kc[mt][j][q] = __fsub_rn(__fsub_rn(t, ks[mt][j][q]), y);
                        ks[mt][j][q] = t;
                        acc[mt][j][q] = 0.f;
                    }
        }
    }
#undef GISSUE

    // nPh is even (12 or 24) so all chunks are folded; result = ks - kc
    float* plane = g_P + (size_t)blockIdx.y * (Bc * Nc);
#pragma unroll
    for (int mt = 0; mt < 2; mt++)
#pragma unroll
        for (int j = 0; j < 4; j++) {
            int m = wm * 32 + mt * 16 + g;
            int n = bn + wn * 32 + j * 8 + 2 * tig;
            float r0 = __fsub_rn(ks[mt][j][0], kc[mt][j][0]);
            float r1 = __fsub_rn(ks[mt][j][1], kc[mt][j][1]);
            float r2 = __fsub_rn(ks[mt][j][2], kc[mt][j][2]);
            float r3 = __fsub_rn(ks[mt][j][3], kc[mt][j][3]);
            *(float2*)&plane[(size_t)m * Nc + n]       = make_float2(r0, r1);
            *(float2*)&plane[(size_t)(m + 8) * Nc + n] = make_float2(r2, r3);
        }
}

// ---------------------------------------------------------------------------
__global__ void scan_kernel(const float* __restrict__ thr, int l,
                            float* __restrict__ R) {
    int idx = blockIdx.x * blockDim.x + threadIdx.x;
    if (idx >= Bc * Nc) return;
    float e[8];
#pragma unroll
    for (int p = 0; p < 8; p++) e[p] = g_P[p * (Bc * Nc) + idx];
#pragma unroll
    for (int s = 1; s < 8; s <<= 1)
#pragma unroll
        for (int p = 0; p < 8; p += 2 * s) e[p] = __fadd_rn(e[p], e[p + s]);
    R[idx] = spike_count(e[0] * 0.015625f, thr[l]);   // /64 exact
}

__global__ void out_kernel(const float* __restrict__ R,
                           const int* __restrict__ out_idx,
                           float* __restrict__ out) {
    int idx = blockIdx.x * blockDim.x + threadIdx.x;
    if (idx >= Bc * OUTc) return;
    int b = idx >> 10, o = idx & 1023;
    out[idx] = R[(b << 11) + out_idx[o]];              // already counts
}

// ---------------------------------------------------------------------------
extern "C" void kernel_launch(void* const* d_in, const int* in_sizes, int n_in,
                              void* d_out, int out_size)
{
    const float* x       = (const float*)d_in[0];
    const float* W       = (const float*)d_in[1];
    const float* thr     = (const float*)d_in[2];
    const int*   axon    = (const int*)  d_in[3];
    const int*   out_idx = (const int*)  d_in[4];
    (void)in_sizes; (void)n_in; (void)out_size;

    cudaFuncSetAttribute(gemm_kernel,
                         cudaFuncAttributeMaxDynamicSharedMemorySize, SMEMB);

    float *R0, *R1;
    cudaGetSymbolAddress((void**)&R0, g_R0);
    cudaGetSymbolAddress((void**)&R1, g_R1);

    dim3 gg(32, 8);   // 32 n-blocks x splitK 8 = 256 blocks

    // layer 0
    asplit0_kernel<<<1024, 256>>>(x, axon);
    wsplit0_kernel<<<16384, 256>>>(W);
    gemm_kernel<<<gg, GT, SMEMB>>>(KT0, 24);
    scan_kernel<<<1024, 256>>>(thr, 0, R0);

    const float* rin = R0;
    for (int l = 1; l < 4; l++) {
        agather1_kernel<<<512, 256>>>(rin, axon + l * Dc);
        wsplit1_kernel<<<8192, 256>>>(W + (size_t)l * Nc * Dc);
        gemm_kernel<<<gg, GT, SMEMB>>>(KT1, 12);
        float* rout = (l & 1) ? R1 : R0;
        scan_kernel<<<1024, 256>>>(thr, l, rout);
        rin = rout;
    }
    out_kernel<<<512, 256>>>(rin, out_idx, (float*)d_out);
}

// round 10
// speedup vs baseline: 1.8853x; 1.2034x over previous
#include <cuda_runtime.h>
#include <cuda_bf16.h>
#include <cstdint>

// ---------------------------------------------------------------------------
// StableSpikingCoreFlow, round 10: tensor-core bf16 GEMM, exact products,
// chunked+Kahan accumulation (rel_err-0.0 class), splitK=4, piece-major B
// with A-reuse for layers>=1, fused prep kernels.
// ---------------------------------------------------------------------------

#define Bc 128
#define Dc 2048
#define Nc 2048
#define Tc 64
#define OUTc 1024
#define SPLITK 4

#define KT0 12288            // layer-0 interleaved slot count
#define GT  256

#define ROWB 144             // 64 bf16 (128B) + 16B pad
#define ATILE (128 * ROWB)   // 18432 B
#define BTILE0 (64 * ROWB)   //  9216 B
#define BUF0  (ATILE + BTILE0)
#define SMEM0 (2 * BUF0)     // 55296 B
#define BTILE1 (3 * 64 * ROWB)
#define BUF1  (ATILE + BTILE1)
#define SMEM1 (2 * BUF1)     // 92160 B

__device__ __nv_bfloat16 g_A[(size_t)Bc * KT0];
__device__ __nv_bfloat16 g_B[(size_t)Nc * KT0];
__device__ float g_P[SPLITK * Bc * Nc];
__device__ float g_R0[Bc * Nc];
__device__ float g_R1[Bc * Nc];

// ---------------------------------------------------------------------------
__device__ __forceinline__ void cp16(uint32_t dst, const void* src) {
    asm volatile("cp.async.cg.shared.global [%0], [%1], 16;\n" :: "r"(dst), "l"(src));
}
#define CP_COMMIT() asm volatile("cp.async.commit_group;\n" ::: "memory")
#define CP_WAIT(n)  asm volatile("cp.async.wait_group %0;\n" :: "n"(n) : "memory")

__device__ __forceinline__ void mma16816(float* c, const uint32_t* a,
                                         uint32_t b0, uint32_t b1) {
    asm volatile(
        "mma.sync.aligned.m16n8k16.row.col.f32.bf16.bf16.f32 "
        "{%0,%1,%2,%3},{%4,%5,%6,%7},{%8,%9},{%0,%1,%2,%3};\n"
        : "+f"(c[0]), "+f"(c[1]), "+f"(c[2]), "+f"(c[3])
        : "r"(a[0]), "r"(a[1]), "r"(a[2]), "r"(a[3]), "r"(b0), "r"(b1));
}

__device__ __forceinline__ float bfround(float v) {
    return __bfloat162float(__float2bfloat16_rn(v));
}
__device__ __forceinline__ unsigned bfu(float v) {
    return (unsigned)__bfloat16_as_ushort(__float2bfloat16_rn(v));
}
__device__ __forceinline__ uint32_t pk(unsigned lo, unsigned hi) {
    return lo | (hi << 16);
}
// v = p0+p1+p2 + O(2^-25 v); residual subtractions exact
__device__ __forceinline__ void split3(float v, unsigned& u0, unsigned& u1,
                                       unsigned& u2) {
    float r1 = v - bfround(v);
    float r2 = r1 - bfround(r1);
    u0 = bfu(v); u1 = bfu(r1); u2 = bfu(r2);
}

// exact fp32 semantics of the reference spike scan; returns COUNT (0..64)
__device__ __forceinline__ float spike_count(float a, float thr) {
    int c;
    if (a <= 0.f) c = 0;
    else if (a > thr) c = Tc;
    else {
        float m = 0.f; c = 0;
        for (int t = 0; t < Tc; t++) { m += a; if (m > thr) { m -= thr; c++; } }
    }
    return (float)c;
}

// ---------------------------------------------------------------------------
// layer-0 prep: A' slots [v0,v0,v0,v1,v1,v2] of v=64*x gathered; B' slots
// [w0,w1,w2,w0,w1,w0]  (pairs (0,0)(0,1)(0,2)(1,0)(1,1)(2,0)).
__global__ void prep0_kernel(const float* __restrict__ x,
                             const int* __restrict__ axon,
                             const float* __restrict__ W) {
    int idx = blockIdx.x * blockDim.x + threadIdx.x;
    if (idx < Bc * Dc) {
        int b = idx >> 11, a = idx & 2047;
        unsigned u0, u1, u2;
        split3(64.0f * x[(b << 11) + axon[a]], u0, u1, u2);
        uint32_t* dst = (uint32_t*)(g_A + (size_t)b * KT0 + 6 * a);
        dst[0] = pk(u0, u0); dst[1] = pk(u0, u1); dst[2] = pk(u1, u2);
    } else {
        int i = idx - Bc * Dc;
        if (i >= Nc * Dc) return;
        int n = i >> 11, k = i & 2047;
        unsigned u0, u1, u2;
        split3(W[i], u0, u1, u2);
        uint32_t* dst = (uint32_t*)(g_B + (size_t)n * KT0 + 6 * k);
        dst[0] = pk(u0, u1); dst[1] = pk(u2, u0); dst[2] = pk(u1, u0);
    }
}

// layers>=1 prep: A = counts (exact bf16) at K=2048; B piece-major rows
// [w0(0..2047) | w1 | w2] (row length 6144). 2 k per thread (u32 writes).
__global__ void prep1_kernel(const float* __restrict__ R,
                             const int* __restrict__ axon,
                             const float* __restrict__ W) {
    int idx = blockIdx.x * blockDim.x + threadIdx.x;
    if (idx < Bc * Dc / 2) {
        int b = idx >> 10, a = (idx & 1023) * 2;
        unsigned h0 = bfu(R[(b << 11) + axon[a]]);
        unsigned h1 = bfu(R[(b << 11) + axon[a + 1]]);
        *(uint32_t*)(g_A + (size_t)b * Dc + a) = pk(h0, h1);
    } else {
        int i = idx - Bc * Dc / 2;
        if (i >= Nc * Dc / 2) return;
        int n = i >> 10, k = (i & 1023) * 2;
        unsigned a0, a1, a2, b0, b1, b2;
        split3(W[(size_t)n * Dc + k], a0, a1, a2);
        split3(W[(size_t)n * Dc + k + 1], b0, b1, b2);
        __nv_bfloat16* row = g_B + (size_t)n * 6144;
        *(uint32_t*)(row + k)        = pk(a0, b0);
        *(uint32_t*)(row + 2048 + k) = pk(a1, b1);
        *(uint32_t*)(row + 4096 + k) = pk(a2, b2);
    }
}

// ---------------------------------------------------------------------------
// layer-0 GEMM: interleaved slots, Ktot=12288, splitK=4 (slice 3072, 48
// phases of 64 slots), Kahan fold every 2 phases (128 slots).
__global__ __launch_bounds__(GT, 1)
void gemm0_kernel() {
    extern __shared__ char smch[];
    const int tid = threadIdx.x;
    const int w = tid >> 5, lane = tid & 31;
    const int wm = w & 3, wn = w >> 2;
    const int g = lane >> 2, tig = lane & 3;
    const int bn = blockIdx.x * 64;
    const size_t k0 = (size_t)blockIdx.y * (KT0 / SPLITK);
    const uint32_t smb = (uint32_t)__cvta_generic_to_shared(smch);
    const int nPh = (KT0 / SPLITK) / 64;   // 48

    const __nv_bfloat16* srcs[6];
    uint32_t dsts[6];
    const int ch = tid & 7;
#pragma unroll
    for (int r = 0; r < 4; r++) {
        int row = (tid + r * GT) >> 3;
        srcs[r] = g_A + (size_t)row * KT0 + k0 + ch * 8;
        dsts[r] = smb + row * ROWB + ch * 16;
    }
#pragma unroll
    for (int r = 4; r < 6; r++) {
        int brow = (tid + (r - 4) * GT) >> 3;
        srcs[r] = g_B + (size_t)(bn + brow) * KT0 + k0 + ch * 8;
        dsts[r] = smb + ATILE + brow * ROWB + ch * 16;
    }
#define G0ISSUE(p, buf) do {                                        \
        uint32_t bo = (uint32_t)(buf) * BUF0;                       \
        _Pragma("unroll")                                           \
        for (int r = 0; r < 6; r++)                                 \
            cp16(dsts[r] + bo, srcs[r] + (size_t)(p) * 64);         \
        CP_COMMIT();                                                \
    } while (0)

    float acc[2][4][4], ks[2][4][4], kc[2][4][4];
#pragma unroll
    for (int mt = 0; mt < 2; mt++)
#pragma unroll
        for (int j = 0; j < 4; j++)
#pragma unroll
            for (int q = 0; q < 4; q++) {
                acc[mt][j][q] = 0.f; ks[mt][j][q] = 0.f; kc[mt][j][q] = 0.f;
            }

    G0ISSUE(0, 0);
    G0ISSUE(1, 1);

    for (int p = 0; p < nPh; p++) {
        if (p + 1 < nPh) { CP_WAIT(1); } else { CP_WAIT(0); }
        __syncthreads();
        const char* Ab = smch + (p & 1) * BUF0;
        const char* Bb = Ab + ATILE;
#pragma unroll
        for (int kk = 0; kk < 4; kk++) {
            uint32_t a[2][4];
#pragma unroll
            for (int mt = 0; mt < 2; mt++) {
                const char* ap = Ab + (wm * 32 + mt * 16 + g) * ROWB
                               + kk * 32 + tig * 4;
                a[mt][0] = *(const uint32_t*)ap;
                a[mt][1] = *(const uint32_t*)(ap + 8 * ROWB);
                a[mt][2] = *(const uint32_t*)(ap + 16);
                a[mt][3] = *(const uint32_t*)(ap + 8 * ROWB + 16);
            }
#pragma unroll
            for (int j = 0; j < 4; j++) {
                const char* bp = Bb + (wn * 32 + j * 8 + g) * ROWB
                               + kk * 32 + tig * 4;
                uint32_t b0 = *(const uint32_t*)bp;
                uint32_t b1 = *(const uint32_t*)(bp + 16);
                mma16816(acc[0][j], a[0], b0, b1);
                mma16816(acc[1][j], a[1], b0, b1);
            }
        }
        __syncthreads();
        if (p + 2 < nPh) G0ISSUE(p + 2, p & 1);

        if (p & 1) {
#pragma unroll
            for (int mt = 0; mt < 2; mt++)
#pragma unroll
                for (int j = 0; j < 4; j++)
#pragma unroll
                    for (int q = 0; q < 4; q++) {
                        float y = __fsub_rn(acc[mt][j][q], kc[mt][j][q]);
                        float t = __fadd_rn(ks[mt][j][q], y);
                        kc[mt][j][q] = __fsub_rn(__fsub_rn(t, ks[mt][j][q]), y);
                        ks[mt][j][q] = t;
                        acc[mt][j][q] = 0.f;
                    }
        }
    }
#undef G0ISSUE

    float* plane = g_P + (size_t)blockIdx.y * (Bc * Nc);
#pragma unroll
    for (int mt = 0; mt < 2; mt++)
#pragma unroll
        for (int j = 0; j < 4; j++) {
            int m = wm * 32 + mt * 16 + g;
            int n = bn + wn * 32 + j * 8 + 2 * tig;
            float r0 = __fsub_rn(ks[mt][j][0], kc[mt][j][0]);
            float r1 = __fsub_rn(ks[mt][j][1], kc[mt][j][1]);
            float r2 = __fsub_rn(ks[mt][j][2], kc[mt][j][2]);
            float r3 = __fsub_rn(ks[mt][j][3], kc[mt][j][3]);
            *(float2*)&plane[(size_t)m * Nc + n]       = make_float2(r0, r1);
            *(float2*)&plane[(size_t)(m + 8) * Nc + n] = make_float2(r2, r3);
        }
}

// ---------------------------------------------------------------------------
// layers>=1 GEMM: A counts (K=2048, slice 512, 8 phases of 64 cols), B piece-
// major; per phase the A smem tile is used against all 3 B pieces. Kahan
// fold after every phase (64 main products + small corrections per chunk).
__global__ __launch_bounds__(GT, 1)
void gemm1_kernel() {
    extern __shared__ char smch[];
    const int tid = threadIdx.x;
    const int w = tid >> 5, lane = tid & 31;
    const int wm = w & 3, wn = w >> 2;
    const int g = lane >> 2, tig = lane & 3;
    const int bn = blockIdx.x * 64;
    const size_t k0 = (size_t)blockIdx.y * (Dc / SPLITK);   // 512-col slice
    const uint32_t smb = (uint32_t)__cvta_generic_to_shared(smch);
    const int nPh = (Dc / SPLITK) / 64;   // 8

    const __nv_bfloat16* srcs[10];
    uint32_t dsts[10];
    const int ch = tid & 7;
#pragma unroll
    for (int r = 0; r < 4; r++) {                  // A: 1024 chunks
        int row = (tid + r * GT) >> 3;
        srcs[r] = g_A + (size_t)row * Dc + k0 + ch * 8;
        dsts[r] = smb + row * ROWB + ch * 16;
    }
#pragma unroll
    for (int pc = 0; pc < 3; pc++)                 // B: 3 x 512 chunks
#pragma unroll
        for (int r = 0; r < 2; r++) {
            int brow = (tid + r * GT) >> 3;
            srcs[4 + pc * 2 + r] = g_B + (size_t)(bn + brow) * 6144
                                 + pc * 2048 + k0 + ch * 8;
            dsts[4 + pc * 2 + r] = smb + ATILE + pc * (64 * ROWB)
                                 + brow * ROWB + ch * 16;
        }
#define G1ISSUE(p, buf) do {                                        \
        uint32_t bo = (uint32_t)(buf) * BUF1;                       \
        _Pragma("unroll")                                           \
        for (int r = 0; r < 10; r++)                                \
            cp16(dsts[r] + bo, srcs[r] + (size_t)(p) * 64);         \
        CP_COMMIT();                                                \
    } while (0)

    float acc[2][4][4], ks[2][4][4], kc[2][4][4];
#pragma unroll
    for (int mt = 0; mt < 2; mt++)
#pragma unroll
        for (int j = 0; j < 4; j++)
#pragma unroll
            for (int q = 0; q < 4; q++) {
                acc[mt][j][q] = 0.f; ks[mt][j][q] = 0.f; kc[mt][j][q] = 0.f;
            }

    G1ISSUE(0, 0);
    G1ISSUE(1, 1);

    for (int p = 0; p < nPh; p++) {
        if (p + 1 < nPh) { CP_WAIT(1); } else { CP_WAIT(0); }
        __syncthreads();
        const char* Ab = smch + (p & 1) * BUF1;
        const char* Bb = Ab + ATILE;
#pragma unroll
        for (int kk = 0; kk < 4; kk++) {
            uint32_t a[2][4];
#pragma unroll
            for (int mt = 0; mt < 2; mt++) {
                const char* ap = Ab + (wm * 32 + mt * 16 + g) * ROWB
                               + kk * 32 + tig * 4;
                a[mt][0] = *(const uint32_t*)ap;
                a[mt][1] = *(const uint32_t*)(ap + 8 * ROWB);
                a[mt][2] = *(const uint32_t*)(ap + 16);
                a[mt][3] = *(const uint32_t*)(ap + 8 * ROWB + 16);
            }
#pragma unroll
            for (int pc = 0; pc < 3; pc++) {
#pragma unroll
                for (int j = 0; j < 4; j++) {
                    const char* bp = Bb + pc * (64 * ROWB)
                                   + (wn * 32 + j * 8 + g) * ROWB
                                   + kk * 32 + tig * 4;
                    uint32_t b0 = *(const uint32_t*)bp;
                    uint32_t b1 = *(const uint32_t*)(bp + 16);
                    mma16816(acc[0][j], a[0], b0, b1);
                    mma16816(acc[1][j], a[1], b0, b1);
                }
            }
        }
        __syncthreads();
        if (p + 2 < nPh) G1ISSUE(p + 2, p & 1);

        // Kahan fold every phase (chunk = 64 main products + corrections)
#pragma unroll
        for (int mt = 0; mt < 2; mt++)
#pragma unroll
            for (int j = 0; j < 4; j++)
#pragma unroll
                for (int q = 0; q < 4; q++) {
                    float y = __fsub_rn(acc[mt][j][q], kc[mt][j][q]);
                    float t = __fadd_rn(ks[mt][j][q], y);
                    kc[mt][j][q] = __fsub_rn(__fsub_rn(t, ks[mt][j][q]), y);
                    ks[mt][j][q] = t;
                    acc[mt][j][q] = 0.f;
                }
    }
#undef G1ISSUE

    float* plane = g_P + (size_t)blockIdx.y * (Bc * Nc);
#pragma unroll
    for (int mt = 0; mt < 2; mt++)
#pragma unroll
        for (int j = 0; j < 4; j++) {
            int m = wm * 32 + mt * 16 + g;
            int n = bn + wn * 32 + j * 8 + 2 * tig;
            float r0 = __fsub_rn(ks[mt][j][0], kc[mt][j][0]);
            float r1 = __fsub_rn(ks[mt][j][1], kc[mt][j][1]);
            float r2 = __fsub_rn(ks[mt][j][2], kc[mt][j][2]);
            float r3 = __fsub_rn(ks[mt][j][3], kc[mt][j][3]);
            *(float2*)&plane[(size_t)m * Nc + n]       = make_float2(r0, r1);
            *(float2*)&plane[(size_t)(m + 8) * Nc + n] = make_float2(r2, r3);
        }
}

// ---------------------------------------------------------------------------
__global__ void scan_kernel(const float* __restrict__ thr, int l,
                            float* __restrict__ R) {
    int idx = blockIdx.x * blockDim.x + threadIdx.x;
    if (idx >= Bc * Nc) return;
    float e0 = g_P[0 * (Bc * Nc) + idx];
    float e1 = g_P[1 * (Bc * Nc) + idx];
    float e2 = g_P[2 * (Bc * Nc) + idx];
    float e3 = g_P[3 * (Bc * Nc) + idx];
    float s = __fadd_rn(__fadd_rn(e0, e1), __fadd_rn(e2, e3));
    R[idx] = spike_count(s * 0.015625f, thr[l]);   // /64 exact
}

__global__ void out_kernel(const float* __restrict__ R,
                           const int* __restrict__ out_idx,
                           float* __restrict__ out) {
    int idx = blockIdx.x * blockDim.x + threadIdx.x;
    if (idx >= Bc * OUTc) return;
    int b = idx >> 10, o = idx & 1023;
    out[idx] = R[(b << 11) + out_idx[o]];          // already counts
}

// ---------------------------------------------------------------------------
extern "C" void kernel_launch(void* const* d_in, const int* in_sizes, int n_in,
                              void* d_out, int out_size)
{
    const float* x       = (const float*)d_in[0];
    const float* W       = (const float*)d_in[1];
    const float* thr     = (const float*)d_in[2];
    const int*   axon    = (const int*)  d_in[3];
    const int*   out_idx = (const int*)  d_in[4];
    (void)in_sizes; (void)n_in; (void)out_size;

    cudaFuncSetAttribute(gemm0_kernel,
                         cudaFuncAttributeMaxDynamicSharedMemorySize, SMEM0);
    cudaFuncSetAttribute(gemm1_kernel,
                         cudaFuncAttributeMaxDynamicSharedMemorySize, SMEM1);

    float *R0, *R1;
    cudaGetSymbolAddress((void**)&R0, g_R0);
    cudaGetSymbolAddress((void**)&R1, g_R1);

    dim3 gg(32, SPLITK);   // 128 blocks

    // layer 0
    prep0_kernel<<<(Bc * Dc + Nc * Dc + 255) / 256, 256>>>(x, axon, W);
    gemm0_kernel<<<gg, GT, SMEM0>>>();
    scan_kernel<<<1024, 256>>>(thr, 0, R0);

    const float* rin = R0;
    for (int l = 1; l < 4; l++) {
        prep1_kernel<<<(Bc * Dc / 2 + Nc * Dc / 2 + 255) / 256, 256>>>(
            rin, axon + l * Dc, W + (size_t)l * Nc * Dc);
        gemm1_kernel<<<gg, GT, SMEM1>>>();
        float* rout = (l & 1) ? R1 : R0;
        scan_kernel<<<1024, 256>>>(thr, l, rout);
        rin = rout;
    }
    out_kernel<<<512, 256>>>(rin, out_idx, (float*)d_out);
}